// round 2
// baseline (speedup 1.0000x reference)
#include <cuda_runtime.h>

#define N_NODES 100000
#define N_EDGES 1600000
#define E_TOT   (N_EDGES + N_NODES)
#define N_GRAPHS 64
#define NEG_SLOPE 0.2f

// ---------------- scratch (device globals; no allocation) ----------------
__device__ float    g_s1[8], g_d1[8];
__device__ int      g_ei_is64, g_b_is64;
__device__ int      g_src[E_TOT];
__device__ int      g_dst[E_TOT];
__device__ int      g_batch[N_NODES];
__device__ unsigned g_max1[N_NODES * 8];
__device__ float    g_den1[N_NODES * 8];
__device__ float    g_t1  [N_NODES * 8];
__device__ float    g_out1[N_NODES * 64];
__device__ float    g_h2  [N_NODES * 128];
__device__ float    g_as2 [N_NODES * 8];
__device__ float    g_ad2 [N_NODES * 8];
__device__ unsigned g_max2[N_NODES * 8];
__device__ float    g_den2[N_NODES * 8];
__device__ float    g_out2[N_NODES * 128];
__device__ float    g_sums[N_GRAPHS * 16];
__device__ float    g_cnt [N_GRAPHS];

// order-preserving float<->uint encoding for atomicMax on floats
__device__ __forceinline__ unsigned enc_f(float f) {
    unsigned u = __float_as_uint(f);
    return (u & 0x80000000u) ? ~u : (u | 0x80000000u);
}
__device__ __forceinline__ float dec_f(unsigned u) {
    return (u & 0x80000000u) ? __uint_as_float(u ^ 0x80000000u)
                             : __uint_as_float(~u);
}
#define ENC_NEG_INF 0x007FFFFFu   // enc(-inf)

__device__ __forceinline__ float lrelu(float v) {
    return v > 0.f ? v : NEG_SLOPE * v;
}

// ---------------- kernels ----------------

// Detect whether edge_index / batch buffers are int64 or int32.
// For int64 non-negative values < 2^31, odd 32-bit words (within the first
// n_elements words, which is always in-bounds) are zero. For int32 random
// edge data they are ~never all zero; for int32 batch the tail words are 63.
__global__ void k_detect(const int* __restrict__ ei,
                         const int* __restrict__ ba) {
    __shared__ int s_e, s_b;
    if (threadIdx.x == 0) { s_e = 1; s_b = 1; }
    __syncthreads();
    int t = threadIdx.x;  // 64 threads
    // edge_index: n_elements = 3.2M; probe odd words spread over [0, 3.2M)
    int we = 2 * (t * 24999 + 13) + 1;          // < 3,200,000
    if (ei[we] != 0) atomicExch(&s_e, 0);
    // batch: n_elements = 100000; probe odd words near the tail
    int wb = (N_NODES - 1) - 2 * t;             // odd indices, in-bounds
    if (ba[wb] != 0) atomicExch(&s_b, 0);
    __syncthreads();
    if (threadIdx.x == 0) { g_ei_is64 = s_e; g_b_is64 = s_b; }
}

__global__ void k_init() {
    int i = blockIdx.x * blockDim.x + threadIdx.x;
    if (i < N_NODES * 8) {
        g_max1[i] = ENC_NEG_INF;
        g_max2[i] = ENC_NEG_INF;
        g_den1[i] = 0.f;
        g_den2[i] = 0.f;
        g_t1[i]   = 0.f;
    }
    if (i < N_NODES * 128) g_out2[i] = 0.f;
    if (i < N_GRAPHS * 16) g_sums[i] = 0.f;
    if (i < N_GRAPHS)      g_cnt[i]  = 0.f;
}

// s1[h] = sum_c W1[h*8+c]*att_src1[h*8+c]; d1 similarly
__global__ void k_prep(const float* __restrict__ W1,
                       const float* __restrict__ att_src1,
                       const float* __restrict__ att_dst1) {
    int t = threadIdx.x;
    if (t < 8) {
        float a = 0.f;
        for (int c = 0; c < 8; c++) a += W1[t * 8 + c] * att_src1[t * 8 + c];
        g_s1[t] = a;
    } else if (t < 16) {
        int h = t - 8;
        float a = 0.f;
        for (int c = 0; c < 8; c++) a += W1[h * 8 + c] * att_dst1[h * 8 + c];
        g_d1[h] = a;
    }
}

__global__ void k_convert(const void* __restrict__ eiv) {
    int i = blockIdx.x * blockDim.x + threadIdx.x;
    if (i >= E_TOT) return;
    if (i < N_EDGES) {
        if (g_ei_is64) {
            const long long* ei = (const long long*)eiv;
            g_src[i] = (int)ei[i];
            g_dst[i] = (int)ei[N_EDGES + i];
        } else {
            const int* ei = (const int*)eiv;
            g_src[i] = ei[i];
            g_dst[i] = ei[N_EDGES + i];
        }
    } else {
        int v = i - N_EDGES;
        g_src[i] = v;
        g_dst[i] = v;
    }
}

__global__ void k_convert_batch(const void* __restrict__ bav) {
    int i = blockIdx.x * blockDim.x + threadIdx.x;
    if (i >= N_NODES) return;
    if (g_b_is64) g_batch[i] = (int)((const long long*)bav)[i];
    else          g_batch[i] = ((const int*)bav)[i];
}

// ---- layer 1 edge passes (rank-1 trick: everything from x scalar) ----
__global__ void k_e1_max(const float* __restrict__ x) {
    int i = blockIdx.x * blockDim.x + threadIdx.x;
    if (i >= E_TOT) return;
    int s = g_src[i], d = g_dst[i];
    float xs = x[s], xd = x[d];
#pragma unroll
    for (int h = 0; h < 8; h++) {
        float e = lrelu(xs * g_s1[h] + xd * g_d1[h]);
        atomicMax(&g_max1[d * 8 + h], enc_f(e));
    }
}

__global__ void k_e1_den(const float* __restrict__ x) {
    int i = blockIdx.x * blockDim.x + threadIdx.x;
    if (i >= E_TOT) return;
    int s = g_src[i], d = g_dst[i];
    float xs = x[s], xd = x[d];
#pragma unroll
    for (int h = 0; h < 8; h++) {
        float e = lrelu(xs * g_s1[h] + xd * g_d1[h]);
        float ex = __expf(e - dec_f(g_max1[d * 8 + h]));
        atomicAdd(&g_den1[d * 8 + h], ex);
    }
}

__global__ void k_e1_agg(const float* __restrict__ x) {
    int i = blockIdx.x * blockDim.x + threadIdx.x;
    if (i >= E_TOT) return;
    int s = g_src[i], d = g_dst[i];
    float xs = x[s], xd = x[d];
#pragma unroll
    for (int h = 0; h < 8; h++) {
        float e = lrelu(xs * g_s1[h] + xd * g_d1[h]);
        float ex = __expf(e - dec_f(g_max1[d * 8 + h]));
        float alpha = ex / g_den1[d * 8 + h];
        atomicAdd(&g_t1[d * 8 + h], alpha * xs);
    }
}

// out1[n,j] = elu(t1[n, j/8] * W1[j] + b1[j])
__global__ void k_node1(const float* __restrict__ W1,
                        const float* __restrict__ b1) {
    int i = blockIdx.x * blockDim.x + threadIdx.x;
    if (i >= N_NODES * 64) return;
    int n = i >> 6, j = i & 63, h = j >> 3;
    float v = g_t1[n * 8 + h] * W1[j] + b1[j];
    g_out1[i] = v > 0.f ? v : (__expf(v) - 1.f);
}

// h2 = out1 @ W2  ([N,64]@[64,128]); one block (128 thr) per node
__global__ void k_gemm2(const float* __restrict__ W2) {
    __shared__ float sin[64];
    int n = blockIdx.x;
    int j = threadIdx.x;
    if (j < 64) sin[j] = g_out1[n * 64 + j];
    __syncthreads();
    float acc = 0.f;
#pragma unroll 8
    for (int k = 0; k < 64; k++) acc += sin[k] * W2[k * 128 + j];
    g_h2[n * 128 + j] = acc;
}

// a_src2[n,h] = dot(h2[n, h*16: h*16+16], att_src2[h]); same for dst
__global__ void k_att2(const float* __restrict__ att_src2,
                       const float* __restrict__ att_dst2) {
    int i = blockIdx.x * blockDim.x + threadIdx.x;
    if (i >= N_NODES * 8) return;
    int n = i >> 3, h = i & 7;
    const float* hp = &g_h2[n * 128 + h * 16];
    float a = 0.f, b = 0.f;
#pragma unroll
    for (int c = 0; c < 16; c++) {
        float v = hp[c];
        a += v * att_src2[h * 16 + c];
        b += v * att_dst2[h * 16 + c];
    }
    g_as2[i] = a;
    g_ad2[i] = b;
}

// ---- layer 2 edge passes ----
__global__ void k_e2_max() {
    int i = blockIdx.x * blockDim.x + threadIdx.x;
    if (i >= E_TOT) return;
    int s = g_src[i], d = g_dst[i];
#pragma unroll
    for (int h = 0; h < 8; h++) {
        float e = lrelu(g_as2[s * 8 + h] + g_ad2[d * 8 + h]);
        atomicMax(&g_max2[d * 8 + h], enc_f(e));
    }
}

__global__ void k_e2_den() {
    int i = blockIdx.x * blockDim.x + threadIdx.x;
    if (i >= E_TOT) return;
    int s = g_src[i], d = g_dst[i];
#pragma unroll
    for (int h = 0; h < 8; h++) {
        float e = lrelu(g_as2[s * 8 + h] + g_ad2[d * 8 + h]);
        float ex = __expf(e - dec_f(g_max2[d * 8 + h]));
        atomicAdd(&g_den2[d * 8 + h], ex);
    }
}

// warp per edge: 32 lanes x float4 = 128 channels
__global__ void k_e2_agg() {
    long long gid = (long long)blockIdx.x * blockDim.x + threadIdx.x;
    int ei = (int)(gid >> 5);
    int lane = (int)(gid & 31);
    if (ei >= E_TOT) return;
    int s = g_src[ei], d = g_dst[ei];
    int h = lane >> 2;
    float e = lrelu(g_as2[s * 8 + h] + g_ad2[d * 8 + h]);
    float alpha = __expf(e - dec_f(g_max2[d * 8 + h])) / g_den2[d * 8 + h];
    const float4 v = *reinterpret_cast<const float4*>(&g_h2[s * 128 + lane * 4]);
    float* o = &g_out2[d * 128 + lane * 4];
    atomicAdd(o + 0, alpha * v.x);
    atomicAdd(o + 1, alpha * v.y);
    atomicAdd(o + 2, alpha * v.z);
    atomicAdd(o + 3, alpha * v.w);
}

// mean over heads + graph pooling accumulation
__global__ void k_pool() {
    int i = blockIdx.x * blockDim.x + threadIdx.x;
    if (i >= N_NODES * 16) return;
    int n = i >> 4, c = i & 15;
    int g = g_batch[n];
    float m = 0.f;
#pragma unroll
    for (int h = 0; h < 8; h++) m += g_out2[n * 128 + h * 16 + c];
    m *= 0.125f;
    atomicAdd(&g_sums[g * 16 + c], m);
    if (c == 0) atomicAdd(&g_cnt[g], 1.f);
}

// pooled = sums/cnt + b2 ; out = pooled @ Wfc + bfc
__global__ void k_final(const float* __restrict__ b2,
                        const float* __restrict__ Wfc,
                        const float* __restrict__ bfc,
                        float* __restrict__ out) {
    int g = threadIdx.x;
    if (g >= N_GRAPHS) return;
    float cnt = g_cnt[g];
    float inv = 1.f / fmaxf(cnt, 1.f);
    float acc[4] = {bfc[0], bfc[1], bfc[2], bfc[3]};
#pragma unroll
    for (int c = 0; c < 16; c++) {
        float p = g_sums[g * 16 + c] * inv + b2[c];
#pragma unroll
        for (int o = 0; o < 4; o++) acc[o] += p * Wfc[c * 4 + o];
    }
#pragma unroll
    for (int o = 0; o < 4; o++) out[g * 4 + o] = acc[o];
}

// ---------------- launch ----------------
extern "C" void kernel_launch(void* const* d_in, const int* in_sizes, int n_in,
                              void* d_out, int out_size) {
    const float* x        = (const float*)d_in[0];
    const float* W1       = (const float*)d_in[1];
    const float* att_src1 = (const float*)d_in[2];
    const float* att_dst1 = (const float*)d_in[3];
    const float* b1       = (const float*)d_in[4];
    const float* W2       = (const float*)d_in[5];
    const float* att_src2 = (const float*)d_in[6];
    const float* att_dst2 = (const float*)d_in[7];
    const float* b2       = (const float*)d_in[8];
    const float* Wfc      = (const float*)d_in[9];
    const float* bfc      = (const float*)d_in[10];
    const void*  ei       = d_in[11];
    const void*  batch    = d_in[12];
    float* out = (float*)d_out;

    const int T = 256;
    k_detect<<<1, 64>>>((const int*)ei, (const int*)batch);
    k_init<<<(N_NODES * 128 + T - 1) / T, T>>>();
    k_prep<<<1, 32>>>(W1, att_src1, att_dst1);
    k_convert<<<(E_TOT + T - 1) / T, T>>>(ei);
    k_convert_batch<<<(N_NODES + T - 1) / T, T>>>(batch);

    int eb = (E_TOT + T - 1) / T;
    k_e1_max<<<eb, T>>>(x);
    k_e1_den<<<eb, T>>>(x);
    k_e1_agg<<<eb, T>>>(x);
    k_node1<<<(N_NODES * 64 + T - 1) / T, T>>>(W1, b1);
    k_gemm2<<<N_NODES, 128>>>(W2);
    k_att2<<<(N_NODES * 8 + T - 1) / T, T>>>(att_src2, att_dst2);
    k_e2_max<<<eb, T>>>();
    k_e2_den<<<eb, T>>>();
    long long tot = (long long)E_TOT * 32;
    k_e2_agg<<<(unsigned)((tot + T - 1) / T), T>>>();
    k_pool<<<(N_NODES * 16 + T - 1) / T, T>>>();
    k_final<<<1, 64>>>(b2, Wfc, bfc, out);
}

// round 3
// speedup vs baseline: 2.4349x; 2.4349x over previous
#include <cuda_runtime.h>

#define N_NODES 100000
#define N_EDGES 1600000
#define E_TOT   (N_EDGES + N_NODES)
#define N_GRAPHS 64
#define NEG_SLOPE 0.2f
#define NEG_BIG  -1e30f

// ---------------- scratch (device globals; no allocation) ----------------
__device__ float    g_s1[8], g_d1[8];
__device__ int      g_ei_is64, g_b_is64;
__device__ int      g_src[E_TOT];
__device__ int      g_dst[E_TOT];
__device__ int      g_batch[N_NODES];
__device__ int      g_deg[N_NODES];
__device__ int      g_rowstart[N_NODES + 1];
__device__ int      g_cursor[N_NODES];
__device__ int      g_csr_src[E_TOT];
__device__ float    g_t1  [N_NODES * 8];
__device__ float    g_h2  [N_NODES * 128];
__device__ float    g_as2 [N_NODES * 8];
__device__ float    g_ad2 [N_NODES * 8];
__device__ float    g_sums[N_GRAPHS * 16];
__device__ float    g_cnt [N_GRAPHS];

__device__ __forceinline__ float lrelu(float v) {
    return v > 0.f ? v : NEG_SLOPE * v;
}

// packed f32x2 helpers
__device__ __forceinline__ unsigned long long pack2(float lo, float hi) {
    unsigned long long r;
    asm("mov.b64 %0, {%1, %2};" : "=l"(r) : "f"(lo), "f"(hi));
    return r;
}
__device__ __forceinline__ void unpack2(unsigned long long p, float& lo, float& hi) {
    asm("mov.b64 {%0, %1}, %2;" : "=f"(lo), "=f"(hi) : "l"(p));
}
__device__ __forceinline__ void ffma2(unsigned long long& acc,
                                      unsigned long long a,
                                      unsigned long long b) {
    asm("fma.rn.f32x2 %0, %1, %2, %0;" : "+l"(acc) : "l"(a), "l"(b));
}

// ---------------- kernels ----------------

// Detect whether edge_index / batch buffers are int64 or int32.
__global__ void k_detect(const int* __restrict__ ei,
                         const int* __restrict__ ba) {
    __shared__ int s_e, s_b;
    if (threadIdx.x == 0) { s_e = 1; s_b = 1; }
    __syncthreads();
    int t = threadIdx.x;  // 64 threads
    int we = 2 * (t * 24999 + 13) + 1;          // < 3,200,000
    if (ei[we] != 0) atomicExch(&s_e, 0);
    int wb = (N_NODES - 1) - 2 * t;             // odd indices, in-bounds
    if (ba[wb] != 0) atomicExch(&s_b, 0);
    __syncthreads();
    if (threadIdx.x == 0) { g_ei_is64 = s_e; g_b_is64 = s_b; }
}

__global__ void k_init() {
    int i = blockIdx.x * blockDim.x + threadIdx.x;
    if (i < N_NODES) g_deg[i] = 0;
    if (i < N_GRAPHS * 16) g_sums[i] = 0.f;
    if (i < N_GRAPHS)      g_cnt[i]  = 0.f;
}

// s1[h] = sum_c W1[h*8+c]*att_src1[h*8+c]; d1 similarly
__global__ void k_prep(const float* __restrict__ W1,
                       const float* __restrict__ att_src1,
                       const float* __restrict__ att_dst1) {
    int t = threadIdx.x;
    if (t < 8) {
        float a = 0.f;
        for (int c = 0; c < 8; c++) a += W1[t * 8 + c] * att_src1[t * 8 + c];
        g_s1[t] = a;
    } else if (t < 16) {
        int h = t - 8;
        float a = 0.f;
        for (int c = 0; c < 8; c++) a += W1[h * 8 + c] * att_dst1[h * 8 + c];
        g_d1[h] = a;
    }
}

// convert + degree histogram (fused)
__global__ void k_convert(const void* __restrict__ eiv) {
    int i = blockIdx.x * blockDim.x + threadIdx.x;
    if (i >= E_TOT) return;
    int s, d;
    if (i < N_EDGES) {
        if (g_ei_is64) {
            const long long* ei = (const long long*)eiv;
            s = (int)ei[i];
            d = (int)ei[N_EDGES + i];
        } else {
            const int* ei = (const int*)eiv;
            s = ei[i];
            d = ei[N_EDGES + i];
        }
    } else {
        s = i - N_EDGES;
        d = s;
    }
    g_src[i] = s;
    g_dst[i] = d;
    atomicAdd(&g_deg[d], 1);
}

__global__ void k_convert_batch(const void* __restrict__ bav) {
    int i = blockIdx.x * blockDim.x + threadIdx.x;
    if (i >= N_NODES) return;
    if (g_b_is64) g_batch[i] = (int)((const long long*)bav)[i];
    else          g_batch[i] = ((const int*)bav)[i];
}

// exclusive scan of g_deg -> g_rowstart / g_cursor (single block, 1024 thr)
__global__ void k_scan() {
    __shared__ int sh[1024];
    __shared__ int carry;
    int t = threadIdx.x;
    if (t == 0) carry = 0;
    __syncthreads();
    for (int base = 0; base < N_NODES; base += 1024) {
        int i = base + t;
        int v = (i < N_NODES) ? g_deg[i] : 0;
        sh[t] = v;
        __syncthreads();
        for (int off = 1; off < 1024; off <<= 1) {
            int tmp = (t >= off) ? sh[t - off] : 0;
            __syncthreads();
            sh[t] += tmp;
            __syncthreads();
        }
        int excl = sh[t] - v + carry;
        if (i < N_NODES) { g_rowstart[i] = excl; g_cursor[i] = excl; }
        __syncthreads();
        if (t == 1023) carry += sh[1023];
        __syncthreads();
    }
    if (t == 0) g_rowstart[N_NODES] = carry;
}

__global__ void k_scatter() {
    int i = blockIdx.x * blockDim.x + threadIdx.x;
    if (i >= E_TOT) return;
    int d = g_dst[i];
    int p = atomicAdd(&g_cursor[d], 1);
    g_csr_src[p] = g_src[i];
}

// ---- layer 1: single fused pass, one warp per dst node ----
// t1[d,h] = sum_j softmax_j( lrelu(x[s_j]*s1[h] + x[d]*d1[h]) ) * x[s_j]
__global__ void k_l1(const float* __restrict__ x) {
    int w = (blockIdx.x * blockDim.x + threadIdx.x) >> 5;
    if (w >= N_NODES) return;
    int lane = threadIdx.x & 31;
    int eo = lane >> 3, h = lane & 7;
    int start = g_rowstart[w], end = g_rowstart[w + 1];
    float xd = x[w];
    float cs = g_s1[h];
    float cd = g_d1[h] * xd;
    float m = NEG_BIG, den = 0.f, num = 0.f;
    for (int j = start + eo; j < end; j += 4) {
        int s = g_csr_src[j];
        float xs = x[s];
        float e = lrelu(fmaf(xs, cs, cd));
        float nm = fmaxf(m, e);
        float r = __expf(m - nm);
        float wj = __expf(e - nm);
        den = den * r + wj;
        num = num * r + wj * xs;
        m = nm;
    }
#pragma unroll
    for (int off = 8; off <= 16; off <<= 1) {
        float m2 = __shfl_xor_sync(0xffffffffu, m,   off);
        float d2 = __shfl_xor_sync(0xffffffffu, den, off);
        float n2 = __shfl_xor_sync(0xffffffffu, num, off);
        float nm = fmaxf(m, m2);
        float r1 = __expf(m - nm), r2 = __expf(m2 - nm);
        den = den * r1 + d2 * r2;
        num = num * r1 + n2 * r2;
        m = nm;
    }
    if (lane < 8) g_t1[w * 8 + h] = num / den;
}

// ---- GEMM2 with fused elu-of-layer1 input.
// out1[n,j] = elu(t1[n, j>>3]*W1[j] + b1[j]);  h2 = out1 @ W2 ([64,128])
// block: 128 threads, 16 nodes. warp ng handles nodes ng*4.. and all 128 cols.
__global__ void __launch_bounds__(128) k_gemm2(const float* __restrict__ W1,
                                               const float* __restrict__ b1,
                                               const float* __restrict__ W2) {
    __shared__ float s_in[16][64];
    int t = threadIdx.x;
    int n0 = blockIdx.x * 16;
    // stage 1: build elu(out1) tile
    for (int e = t; e < 1024; e += 128) {
        int nn = e >> 6, j = e & 63;
        float v = fmaf(g_t1[(n0 + nn) * 8 + (j >> 3)], W1[j], b1[j]);
        s_in[nn][j] = v > 0.f ? v : (__expf(v) - 1.f);
    }
    __syncthreads();
    int lane = t & 31;
    int ng = t >> 5;            // warp -> node group of 4
    int c = lane * 4;           // 4 columns
    unsigned long long acc01[4], acc23[4];
#pragma unroll
    for (int i = 0; i < 4; i++) { acc01[i] = 0ull; acc23[i] = 0ull; }
    const float* w2p = &W2[c];
#pragma unroll 4
    for (int k = 0; k < 64; k++) {
        float4 wv = *reinterpret_cast<const float4*>(w2p + k * 128);
        unsigned long long s01 = pack2(s_in[ng * 4 + 0][k], s_in[ng * 4 + 1][k]);
        unsigned long long s23 = pack2(s_in[ng * 4 + 2][k], s_in[ng * 4 + 3][k]);
        unsigned long long w0 = pack2(wv.x, wv.x);
        unsigned long long w1 = pack2(wv.y, wv.y);
        unsigned long long w2 = pack2(wv.z, wv.z);
        unsigned long long w3 = pack2(wv.w, wv.w);
        ffma2(acc01[0], w0, s01); ffma2(acc23[0], w0, s23);
        ffma2(acc01[1], w1, s01); ffma2(acc23[1], w1, s23);
        ffma2(acc01[2], w2, s01); ffma2(acc23[2], w2, s23);
        ffma2(acc01[3], w3, s01); ffma2(acc23[3], w3, s23);
    }
    float lo[4], hi[4];
#pragma unroll
    for (int i = 0; i < 4; i++) unpack2(acc01[i], lo[i], hi[i]);
    int nb = n0 + ng * 4;
    *reinterpret_cast<float4*>(&g_h2[(nb + 0) * 128 + c]) = make_float4(lo[0], lo[1], lo[2], lo[3]);
    *reinterpret_cast<float4*>(&g_h2[(nb + 1) * 128 + c]) = make_float4(hi[0], hi[1], hi[2], hi[3]);
#pragma unroll
    for (int i = 0; i < 4; i++) unpack2(acc23[i], lo[i], hi[i]);
    *reinterpret_cast<float4*>(&g_h2[(nb + 2) * 128 + c]) = make_float4(lo[0], lo[1], lo[2], lo[3]);
    *reinterpret_cast<float4*>(&g_h2[(nb + 3) * 128 + c]) = make_float4(hi[0], hi[1], hi[2], hi[3]);
}

// a_src2[n,h] = dot(h2[n, h*16 : h*16+16], att_src2[h]); same for dst
__global__ void k_att2(const float* __restrict__ att_src2,
                       const float* __restrict__ att_dst2) {
    int i = blockIdx.x * blockDim.x + threadIdx.x;
    if (i >= N_NODES * 8) return;
    int n = i >> 3, h = i & 7;
    const float* hp = &g_h2[n * 128 + h * 16];
    float a = 0.f, b = 0.f;
#pragma unroll
    for (int c = 0; c < 16; c++) {
        float v = hp[c];
        a += v * att_src2[h * 16 + c];
        b += v * att_dst2[h * 16 + c];
    }
    g_as2[i] = a;
    g_ad2[i] = b;
}

// ---- layer 2 fused: softmax (pass A) + weighted gather (pass B) +
//      head-mean + graph-pool accumulation. One warp per dst node.
__global__ void k_l2() {
    int d = (blockIdx.x * blockDim.x + threadIdx.x) >> 5;
    if (d >= N_NODES) return;
    int lane = threadIdx.x & 31;
    int start = g_rowstart[d], end = g_rowstart[d + 1];

    // pass A: (m, den) per head; lanes = 4 edge-offsets x 8 heads
    int h = lane & 7, eo = lane >> 3;
    float ad = g_ad2[d * 8 + h];
    float m = NEG_BIG, den = 0.f;
    for (int j = start + eo; j < end; j += 4) {
        int s = g_csr_src[j];
        float e = lrelu(g_as2[s * 8 + h] + ad);
        float nm = fmaxf(m, e);
        den = den * __expf(m - nm) + __expf(e - nm);
        m = nm;
    }
#pragma unroll
    for (int off = 8; off <= 16; off <<= 1) {
        float m2 = __shfl_xor_sync(0xffffffffu, m,   off);
        float d2 = __shfl_xor_sync(0xffffffffu, den, off);
        float nm = fmaxf(m, m2);
        den = den * __expf(m - nm) + d2 * __expf(m2 - nm);
        m = nm;
    }
    // every lane now holds (m, den, ad) for head lane&7
    int hh = lane >> 2;                       // head for pass B
    float mh  = __shfl_sync(0xffffffffu, m,   hh);
    float dh  = __shfl_sync(0xffffffffu, den, hh);
    float adh = __shfl_sync(0xffffffffu, ad,  hh);

    // pass B: acc over edges, lane covers 4 channels of its head
    float ax = 0.f, ay = 0.f, az = 0.f, aw = 0.f;
    int j = start;
    for (; j + 1 < end; j += 2) {
        int s0 = g_csr_src[j];
        int s1 = g_csr_src[j + 1];
        float e0 = lrelu(g_as2[s0 * 8 + hh] + adh);
        float e1 = lrelu(g_as2[s1 * 8 + hh] + adh);
        float4 v0 = *reinterpret_cast<const float4*>(&g_h2[s0 * 128 + lane * 4]);
        float4 v1 = *reinterpret_cast<const float4*>(&g_h2[s1 * 128 + lane * 4]);
        float w0 = __expf(e0 - mh);
        float w1 = __expf(e1 - mh);
        ax += w0 * v0.x + w1 * v1.x;
        ay += w0 * v0.y + w1 * v1.y;
        az += w0 * v0.z + w1 * v1.z;
        aw += w0 * v0.w + w1 * v1.w;
    }
    if (j < end) {
        int s0 = g_csr_src[j];
        float e0 = lrelu(g_as2[s0 * 8 + hh] + adh);
        float4 v0 = *reinterpret_cast<const float4*>(&g_h2[s0 * 128 + lane * 4]);
        float w0 = __expf(e0 - mh);
        ax += w0 * v0.x; ay += w0 * v0.y; az += w0 * v0.z; aw += w0 * v0.w;
    }
    float inv = 0.125f / dh;    // normalize + head-mean factor
    ax *= inv; ay *= inv; az *= inv; aw *= inv;
    // sum across 8 heads (xor over head bits 2,3,4)
#pragma unroll
    for (int off = 4; off <= 16; off <<= 1) {
        ax += __shfl_xor_sync(0xffffffffu, ax, off);
        ay += __shfl_xor_sync(0xffffffffu, ay, off);
        az += __shfl_xor_sync(0xffffffffu, az, off);
        aw += __shfl_xor_sync(0xffffffffu, aw, off);
    }
    int g = g_batch[d];
    if (lane < 4) {
        float* dst = &g_sums[g * 16 + lane * 4];
        atomicAdd(dst + 0, ax);
        atomicAdd(dst + 1, ay);
        atomicAdd(dst + 2, az);
        atomicAdd(dst + 3, aw);
    }
    if (lane == 4) atomicAdd(&g_cnt[g], 1.f);
}

// pooled = sums/cnt + b2 ; out = pooled @ Wfc + bfc
__global__ void k_final(const float* __restrict__ b2,
                        const float* __restrict__ Wfc,
                        const float* __restrict__ bfc,
                        float* __restrict__ out) {
    int g = threadIdx.x;
    if (g >= N_GRAPHS) return;
    float inv = 1.f / fmaxf(g_cnt[g], 1.f);
    float acc[4] = {bfc[0], bfc[1], bfc[2], bfc[3]};
#pragma unroll
    for (int c = 0; c < 16; c++) {
        float p = g_sums[g * 16 + c] * inv + b2[c];
#pragma unroll
        for (int o = 0; o < 4; o++) acc[o] += p * Wfc[c * 4 + o];
    }
#pragma unroll
    for (int o = 0; o < 4; o++) out[g * 4 + o] = acc[o];
}

// ---------------- launch ----------------
extern "C" void kernel_launch(void* const* d_in, const int* in_sizes, int n_in,
                              void* d_out, int out_size) {
    const float* x        = (const float*)d_in[0];
    const float* W1       = (const float*)d_in[1];
    const float* att_src1 = (const float*)d_in[2];
    const float* att_dst1 = (const float*)d_in[3];
    const float* b1       = (const float*)d_in[4];
    const float* W2       = (const float*)d_in[5];
    const float* att_src2 = (const float*)d_in[6];
    const float* att_dst2 = (const float*)d_in[7];
    const float* b2       = (const float*)d_in[8];
    const float* Wfc      = (const float*)d_in[9];
    const float* bfc      = (const float*)d_in[10];
    const void*  ei       = d_in[11];
    const void*  batch    = d_in[12];
    float* out = (float*)d_out;

    const int T = 256;
    k_detect<<<1, 64>>>((const int*)ei, (const int*)batch);
    k_init<<<(N_NODES + T - 1) / T, T>>>();
    k_prep<<<1, 32>>>(W1, att_src1, att_dst1);
    k_convert<<<(E_TOT + T - 1) / T, T>>>(ei);
    k_convert_batch<<<(N_NODES + T - 1) / T, T>>>(batch);
    k_scan<<<1, 1024>>>();
    k_scatter<<<(E_TOT + T - 1) / T, T>>>();

    k_l1<<<(N_NODES * 32 + T - 1) / T, T>>>(x);
    k_gemm2<<<N_NODES / 16, 128>>>(W1, b1, W2);
    k_att2<<<(N_NODES * 8 + T - 1) / T, T>>>(att_src2, att_dst2);
    k_l2<<<(N_NODES * 32 + T - 1) / T, T>>>();
    k_final<<<1, 64>>>(b2, Wfc, bfc, out);
}

// round 4
// speedup vs baseline: 3.1715x; 1.3025x over previous
#include <cuda_runtime.h>

#define N_NODES 100000
#define N_EDGES 1600000
#define E_TOT   (N_EDGES + N_NODES)
#define N_GRAPHS 64
#define NEG_SLOPE 0.2f
#define NEG_BIG  -1e30f
#define SCAN_BLK 1024
#define N_SBLK   ((N_NODES + SCAN_BLK - 1) / SCAN_BLK)   // 98

// ---------------- scratch (device globals; no allocation) ----------------
__device__ float    g_s1[8], g_d1[8];
__device__ int      g_ei_is64, g_b_is64;
__device__ int      g_src[E_TOT];
__device__ int      g_dst[E_TOT];
__device__ int      g_batch[N_NODES];
__device__ int      g_deg[N_NODES];
__device__ int      g_incl[N_NODES];
__device__ int      g_bsum[N_SBLK];
__device__ int      g_boff[N_SBLK];
__device__ int      g_rowstart[N_NODES + 1];
__device__ int      g_cursor[N_NODES];
__device__ int      g_csr_src[E_TOT];
__device__ float    g_t1  [N_NODES * 8];
__device__ float    g_h2  [N_NODES * 128];
__device__ float    g_as2 [N_NODES * 8];
__device__ float    g_ad2 [N_NODES * 8];
__device__ float    g_sums[N_GRAPHS * 16];
__device__ float    g_cnt [N_GRAPHS];

__device__ __forceinline__ float lrelu(float v) {
    return v > 0.f ? v : NEG_SLOPE * v;
}

// packed f32x2 helpers
__device__ __forceinline__ unsigned long long pack2(float lo, float hi) {
    unsigned long long r;
    asm("mov.b64 %0, {%1, %2};" : "=l"(r) : "f"(lo), "f"(hi));
    return r;
}
__device__ __forceinline__ void unpack2(unsigned long long p, float& lo, float& hi) {
    asm("mov.b64 {%0, %1}, %2;" : "=f"(lo), "=f"(hi) : "l"(p));
}
__device__ __forceinline__ void ffma2(unsigned long long& acc,
                                      unsigned long long a,
                                      unsigned long long b) {
    asm("fma.rn.f32x2 %0, %1, %2, %0;" : "+l"(acc) : "l"(a), "l"(b));
}

// ---------------- kernels ----------------

// Detect whether edge_index / batch buffers are int64 or int32.
__global__ void k_detect(const int* __restrict__ ei,
                         const int* __restrict__ ba) {
    __shared__ int s_e, s_b;
    if (threadIdx.x == 0) { s_e = 1; s_b = 1; }
    __syncthreads();
    int t = threadIdx.x;  // 64 threads
    int we = 2 * (t * 24999 + 13) + 1;          // < 3,200,000
    if (ei[we] != 0) atomicExch(&s_e, 0);
    int wb = (N_NODES - 1) - 2 * t;             // odd indices, in-bounds
    if (ba[wb] != 0) atomicExch(&s_b, 0);
    __syncthreads();
    if (threadIdx.x == 0) { g_ei_is64 = s_e; g_b_is64 = s_b; }
}

__global__ void k_init() {
    int i = blockIdx.x * blockDim.x + threadIdx.x;
    if (i < N_NODES) g_deg[i] = 0;
    if (i < N_GRAPHS * 16) g_sums[i] = 0.f;
    if (i < N_GRAPHS)      g_cnt[i]  = 0.f;
    if (i == 0)            g_rowstart[N_NODES] = E_TOT;
}

// s1[h] = sum_c W1[h*8+c]*att_src1[h*8+c]; d1 similarly
__global__ void k_prep(const float* __restrict__ W1,
                       const float* __restrict__ att_src1,
                       const float* __restrict__ att_dst1) {
    int t = threadIdx.x;
    if (t < 8) {
        float a = 0.f;
        for (int c = 0; c < 8; c++) a += W1[t * 8 + c] * att_src1[t * 8 + c];
        g_s1[t] = a;
    } else if (t < 16) {
        int h = t - 8;
        float a = 0.f;
        for (int c = 0; c < 8; c++) a += W1[h * 8 + c] * att_dst1[h * 8 + c];
        g_d1[h] = a;
    }
}

// convert + degree histogram (fused)
__global__ void k_convert(const void* __restrict__ eiv) {
    int i = blockIdx.x * blockDim.x + threadIdx.x;
    if (i >= E_TOT) return;
    int s, d;
    if (i < N_EDGES) {
        if (g_ei_is64) {
            const long long* ei = (const long long*)eiv;
            s = (int)ei[i];
            d = (int)ei[N_EDGES + i];
        } else {
            const int* ei = (const int*)eiv;
            s = ei[i];
            d = ei[N_EDGES + i];
        }
    } else {
        s = i - N_EDGES;
        d = s;
    }
    g_src[i] = s;
    g_dst[i] = d;
    atomicAdd(&g_deg[d], 1);
}

__global__ void k_convert_batch(const void* __restrict__ bav) {
    int i = blockIdx.x * blockDim.x + threadIdx.x;
    if (i >= N_NODES) return;
    if (g_b_is64) g_batch[i] = (int)((const long long*)bav)[i];
    else          g_batch[i] = ((const int*)bav)[i];
}

// ---- two-level scan ----
// stage 1: per-block inclusive scan of deg tiles + block sums
__global__ void k_scan1() {
    __shared__ int sh[SCAN_BLK];
    int t = threadIdx.x;
    int i = blockIdx.x * SCAN_BLK + t;
    int v = (i < N_NODES) ? g_deg[i] : 0;
    sh[t] = v;
    __syncthreads();
#pragma unroll
    for (int off = 1; off < SCAN_BLK; off <<= 1) {
        int tmp = (t >= off) ? sh[t - off] : 0;
        __syncthreads();
        sh[t] += tmp;
        __syncthreads();
    }
    if (i < N_NODES) g_incl[i] = sh[t];
    if (t == SCAN_BLK - 1) g_bsum[blockIdx.x] = sh[t];
}

// stage 2: exclusive scan of the 98 block sums (single block of 128)
__global__ void k_scan2() {
    __shared__ int sh[128];
    int t = threadIdx.x;
    int v = (t < N_SBLK) ? g_bsum[t] : 0;
    sh[t] = v;
    __syncthreads();
#pragma unroll
    for (int off = 1; off < 128; off <<= 1) {
        int tmp = (t >= off) ? sh[t - off] : 0;
        __syncthreads();
        sh[t] += tmp;
        __syncthreads();
    }
    if (t < N_SBLK) g_boff[t] = sh[t] - v;
}

// stage 3: rowstart = incl - deg + blockoff; cursor = rowstart
__global__ void k_scan3() {
    int i = blockIdx.x * blockDim.x + threadIdx.x;
    if (i >= N_NODES) return;
    int rs = g_incl[i] - g_deg[i] + g_boff[i >> 10];
    g_rowstart[i] = rs;
    g_cursor[i]   = rs;
}

__global__ void k_scatter() {
    int i = blockIdx.x * blockDim.x + threadIdx.x;
    if (i >= E_TOT) return;
    int d = g_dst[i];
    int p = atomicAdd(&g_cursor[d], 1);
    g_csr_src[p] = g_src[i];
}

// ---- layer 1: single fused pass, one warp per dst node ----
__global__ void k_l1(const float* __restrict__ x) {
    int w = (blockIdx.x * blockDim.x + threadIdx.x) >> 5;
    if (w >= N_NODES) return;
    int lane = threadIdx.x & 31;
    int eo = lane >> 3, h = lane & 7;
    int start = g_rowstart[w], end = g_rowstart[w + 1];
    float xd = x[w];
    float cs = g_s1[h];
    float cd = g_d1[h] * xd;
    float m = NEG_BIG, den = 0.f, num = 0.f;
    for (int j = start + eo; j < end; j += 4) {
        int s = g_csr_src[j];
        float xs = x[s];
        float e = lrelu(fmaf(xs, cs, cd));
        float nm = fmaxf(m, e);
        float r = __expf(m - nm);
        float wj = __expf(e - nm);
        den = den * r + wj;
        num = num * r + wj * xs;
        m = nm;
    }
#pragma unroll
    for (int off = 8; off <= 16; off <<= 1) {
        float m2 = __shfl_xor_sync(0xffffffffu, m,   off);
        float d2 = __shfl_xor_sync(0xffffffffu, den, off);
        float n2 = __shfl_xor_sync(0xffffffffu, num, off);
        float nm = fmaxf(m, m2);
        float r1 = __expf(m - nm), r2 = __expf(m2 - nm);
        den = den * r1 + d2 * r2;
        num = num * r1 + n2 * r2;
        m = nm;
    }
    if (lane < 8) g_t1[w * 8 + h] = num / den;
}

// ---- GEMM2 with fused elu-of-layer1 input ----
__global__ void __launch_bounds__(128) k_gemm2(const float* __restrict__ W1,
                                               const float* __restrict__ b1,
                                               const float* __restrict__ W2) {
    __shared__ float s_in[16][64];
    int t = threadIdx.x;
    int n0 = blockIdx.x * 16;
    for (int e = t; e < 1024; e += 128) {
        int nn = e >> 6, j = e & 63;
        float v = fmaf(g_t1[(n0 + nn) * 8 + (j >> 3)], W1[j], b1[j]);
        s_in[nn][j] = v > 0.f ? v : (__expf(v) - 1.f);
    }
    __syncthreads();
    int lane = t & 31;
    int ng = t >> 5;
    int c = lane * 4;
    unsigned long long acc01[4], acc23[4];
#pragma unroll
    for (int i = 0; i < 4; i++) { acc01[i] = 0ull; acc23[i] = 0ull; }
    const float* w2p = &W2[c];
#pragma unroll 4
    for (int k = 0; k < 64; k++) {
        float4 wv = *reinterpret_cast<const float4*>(w2p + k * 128);
        unsigned long long s01 = pack2(s_in[ng * 4 + 0][k], s_in[ng * 4 + 1][k]);
        unsigned long long s23 = pack2(s_in[ng * 4 + 2][k], s_in[ng * 4 + 3][k]);
        unsigned long long w0 = pack2(wv.x, wv.x);
        unsigned long long w1 = pack2(wv.y, wv.y);
        unsigned long long w2 = pack2(wv.z, wv.z);
        unsigned long long w3 = pack2(wv.w, wv.w);
        ffma2(acc01[0], w0, s01); ffma2(acc23[0], w0, s23);
        ffma2(acc01[1], w1, s01); ffma2(acc23[1], w1, s23);
        ffma2(acc01[2], w2, s01); ffma2(acc23[2], w2, s23);
        ffma2(acc01[3], w3, s01); ffma2(acc23[3], w3, s23);
    }
    float lo[4], hi[4];
#pragma unroll
    for (int i = 0; i < 4; i++) unpack2(acc01[i], lo[i], hi[i]);
    int nb = n0 + ng * 4;
    *reinterpret_cast<float4*>(&g_h2[(nb + 0) * 128 + c]) = make_float4(lo[0], lo[1], lo[2], lo[3]);
    *reinterpret_cast<float4*>(&g_h2[(nb + 1) * 128 + c]) = make_float4(hi[0], hi[1], hi[2], hi[3]);
#pragma unroll
    for (int i = 0; i < 4; i++) unpack2(acc23[i], lo[i], hi[i]);
    *reinterpret_cast<float4*>(&g_h2[(nb + 2) * 128 + c]) = make_float4(lo[0], lo[1], lo[2], lo[3]);
    *reinterpret_cast<float4*>(&g_h2[(nb + 3) * 128 + c]) = make_float4(hi[0], hi[1], hi[2], hi[3]);
}

// a_src2[n,h] = dot(h2[n, h*16 : h*16+16], att_src2[h]); same for dst
__global__ void k_att2(const float* __restrict__ att_src2,
                       const float* __restrict__ att_dst2) {
    int i = blockIdx.x * blockDim.x + threadIdx.x;
    if (i >= N_NODES * 8) return;
    int n = i >> 3, h = i & 7;
    const float* hp = &g_h2[n * 128 + h * 16];
    float a = 0.f, b = 0.f;
#pragma unroll
    for (int c = 0; c < 16; c++) {
        float v = hp[c];
        a += v * att_src2[h * 16 + c];
        b += v * att_dst2[h * 16 + c];
    }
    g_as2[i] = a;
    g_ad2[i] = b;
}

// ---- layer 2 fused: softmax + weighted gather + head-mean + pool ----
__global__ void k_l2() {
    int d = (blockIdx.x * blockDim.x + threadIdx.x) >> 5;
    if (d >= N_NODES) return;
    int lane = threadIdx.x & 31;
    int start = g_rowstart[d], end = g_rowstart[d + 1];

    // pass A: (m, den) per head; lanes = 4 edge-offsets x 8 heads
    int h = lane & 7, eo = lane >> 3;
    float ad = g_ad2[d * 8 + h];
    float m = NEG_BIG, den = 0.f;
    for (int j = start + eo; j < end; j += 4) {
        int s = g_csr_src[j];
        float e = lrelu(g_as2[s * 8 + h] + ad);
        float nm = fmaxf(m, e);
        den = den * __expf(m - nm) + __expf(e - nm);
        m = nm;
    }
#pragma unroll
    for (int off = 8; off <= 16; off <<= 1) {
        float m2 = __shfl_xor_sync(0xffffffffu, m,   off);
        float d2 = __shfl_xor_sync(0xffffffffu, den, off);
        float nm = fmaxf(m, m2);
        den = den * __expf(m - nm) + d2 * __expf(m2 - nm);
        m = nm;
    }
    int hh = lane >> 2;
    float mh  = __shfl_sync(0xffffffffu, m,   hh);
    float dh  = __shfl_sync(0xffffffffu, den, hh);
    float adh = __shfl_sync(0xffffffffu, ad,  hh);

    // pass B: accumulate weighted h2 rows; lane covers 4 channels of its head
    float ax = 0.f, ay = 0.f, az = 0.f, aw = 0.f;
    int j = start;
    for (; j + 1 < end; j += 2) {
        int s0 = g_csr_src[j];
        int s1 = g_csr_src[j + 1];
        float e0 = lrelu(g_as2[s0 * 8 + hh] + adh);
        float e1 = lrelu(g_as2[s1 * 8 + hh] + adh);
        float4 v0 = *reinterpret_cast<const float4*>(&g_h2[s0 * 128 + lane * 4]);
        float4 v1 = *reinterpret_cast<const float4*>(&g_h2[s1 * 128 + lane * 4]);
        float w0 = __expf(e0 - mh);
        float w1 = __expf(e1 - mh);
        ax += w0 * v0.x + w1 * v1.x;
        ay += w0 * v0.y + w1 * v1.y;
        az += w0 * v0.z + w1 * v1.z;
        aw += w0 * v0.w + w1 * v1.w;
    }
    if (j < end) {
        int s0 = g_csr_src[j];
        float e0 = lrelu(g_as2[s0 * 8 + hh] + adh);
        float4 v0 = *reinterpret_cast<const float4*>(&g_h2[s0 * 128 + lane * 4]);
        float w0 = __expf(e0 - mh);
        ax += w0 * v0.x; ay += w0 * v0.y; az += w0 * v0.z; aw += w0 * v0.w;
    }
    float inv = 0.125f / dh;
    ax *= inv; ay *= inv; az *= inv; aw *= inv;
#pragma unroll
    for (int off = 4; off <= 16; off <<= 1) {
        ax += __shfl_xor_sync(0xffffffffu, ax, off);
        ay += __shfl_xor_sync(0xffffffffu, ay, off);
        az += __shfl_xor_sync(0xffffffffu, az, off);
        aw += __shfl_xor_sync(0xffffffffu, aw, off);
    }
    int g = g_batch[d];
    if (lane < 4) {
        float* dst = &g_sums[g * 16 + lane * 4];
        atomicAdd(dst + 0, ax);
        atomicAdd(dst + 1, ay);
        atomicAdd(dst + 2, az);
        atomicAdd(dst + 3, aw);
    }
    if (lane == 4) atomicAdd(&g_cnt[g], 1.f);
}

// pooled = sums/cnt + b2 ; out = pooled @ Wfc + bfc
__global__ void k_final(const float* __restrict__ b2,
                        const float* __restrict__ Wfc,
                        const float* __restrict__ bfc,
                        float* __restrict__ out) {
    int g = threadIdx.x;
    if (g >= N_GRAPHS) return;
    float inv = 1.f / fmaxf(g_cnt[g], 1.f);
    float acc[4] = {bfc[0], bfc[1], bfc[2], bfc[3]};
#pragma unroll
    for (int c = 0; c < 16; c++) {
        float p = g_sums[g * 16 + c] * inv + b2[c];
#pragma unroll
        for (int o = 0; o < 4; o++) acc[o] += p * Wfc[c * 4 + o];
    }
#pragma unroll
    for (int o = 0; o < 4; o++) out[g * 4 + o] = acc[o];
}

// ---------------- launch ----------------
extern "C" void kernel_launch(void* const* d_in, const int* in_sizes, int n_in,
                              void* d_out, int out_size) {
    const float* x        = (const float*)d_in[0];
    const float* W1       = (const float*)d_in[1];
    const float* att_src1 = (const float*)d_in[2];
    const float* att_dst1 = (const float*)d_in[3];
    const float* b1       = (const float*)d_in[4];
    const float* W2       = (const float*)d_in[5];
    const float* att_src2 = (const float*)d_in[6];
    const float* att_dst2 = (const float*)d_in[7];
    const float* b2       = (const float*)d_in[8];
    const float* Wfc      = (const float*)d_in[9];
    const float* bfc      = (const float*)d_in[10];
    const void*  ei       = d_in[11];
    const void*  batch    = d_in[12];
    float* out = (float*)d_out;

    const int T = 256;
    k_detect<<<1, 64>>>((const int*)ei, (const int*)batch);
    k_init<<<(N_NODES + T - 1) / T, T>>>();
    k_prep<<<1, 32>>>(W1, att_src1, att_dst1);
    k_convert<<<(E_TOT + T - 1) / T, T>>>(ei);
    k_convert_batch<<<(N_NODES + T - 1) / T, T>>>(batch);
    k_scan1<<<N_SBLK, SCAN_BLK>>>();
    k_scan2<<<1, 128>>>();
    k_scan3<<<(N_NODES + T - 1) / T, T>>>();
    k_scatter<<<(E_TOT + T - 1) / T, T>>>();

    k_l1<<<(N_NODES * 32 + T - 1) / T, T>>>(x);
    k_gemm2<<<N_NODES / 16, 128>>>(W1, b1, W2);
    k_att2<<<(N_NODES * 8 + T - 1) / T, T>>>(att_src2, att_dst2);
    k_l2<<<(N_NODES * 32 + T - 1) / T, T>>>();
    k_final<<<1, 64>>>(b2, Wfc, bfc, out);
}